// round 1
// baseline (speedup 1.0000x reference)
#include <cuda_runtime.h>
#include <math.h>

// ---------------- problem constants ----------------
#define BGRAPHS 128
#define N0      1024
#define EMAX    1048576
#define NT1     (BGRAPHS * N0)        // 131072
#define K1      820
#define NT2     (BGRAPHS * K1)        // 104960
#define K2      656
#define NT3     (BGRAPHS * K2)        // 83968
#define K3      525
#define NT4     (BGRAPHS * K3)        // 67200
#define NHID    64
#define NCLS    10

#define EGRID    2048
#define ETHREADS 256

// ---------------- device scratch (static; no allocations allowed) ----------------
__device__ float g_A[NT1 * 64];       // conv output buffer
__device__ float g_B[NT1 * 64];       // pooled features buffer (ping-pong)
__device__ float g_xw[NT1 * 64];      // GEMM output (pre-aggregation)
__device__ float g_deg[NT1];
__device__ float g_dis[NT1];
__device__ float g_dis2[NT1];
__device__ float g_sxw[NT1];          // score pre-aggregation (x @ Wp)
__device__ float g_score[NT1];
__device__ float g_gate[NT1];         // tanh(score) indexed by NEW node id
__device__ float g_enorm[EMAX];
__device__ int   g_es1[EMAX], g_ed1[EMAX];
__device__ int   g_es2[EMAX], g_ed2[EMAX];
__device__ int   g_newidx[NT1];
__device__ int   g_perm[NT1];         // new id -> old id
__device__ int   g_mcnt[2];
__device__ float g_r1[BGRAPHS * 128], g_r2[BGRAPHS * 128], g_r3[BGRAPHS * 128];

// ---------------- kernels ----------------

// deg[i] = 1 (self loop); also zero the compaction counter for this stage.
__global__ void k_stage_init(float* deg, int n, int* mcnt) {
    int i = blockIdx.x * blockDim.x + threadIdx.x;
    if (i < n) deg[i] = 1.0f;
    if (i == 0 && mcnt) *mcnt = 0;
}

__global__ void k_deg_acc(const int* __restrict__ dst, const int* m_ptr, int m_static,
                          float* deg) {
    int m = m_ptr ? *m_ptr : m_static;
    for (int e = blockIdx.x * blockDim.x + threadIdx.x; e < m;
         e += gridDim.x * blockDim.x)
        atomicAdd(&deg[dst[e]], 1.0f);
}

__global__ void k_dis(const float* __restrict__ deg, float* dis, float* dis2, int n) {
    int i = blockIdx.x * blockDim.x + threadIdx.x;
    if (i < n) {
        float s = rsqrtf(deg[i]);
        dis[i] = s;
        dis2[i] = s * s;
    }
}

__global__ void k_enorm(const int* __restrict__ src, const int* __restrict__ dst,
                        const int* m_ptr, int m_static,
                        const float* __restrict__ dis, float* enorm) {
    int m = m_ptr ? *m_ptr : m_static;
    for (int e = blockIdx.x * blockDim.x + threadIdx.x; e < m;
         e += gridDim.x * blockDim.x)
        enorm[e] = dis[src[e]] * dis[dst[e]];
}

// C[n x 64] = A[n x 64] @ W[64 x 64]
__global__ void k_gemm64(const float* __restrict__ A, const float* __restrict__ W,
                         float* __restrict__ C, int n) {
    __shared__ float As[64][64];
    __shared__ float Ws[64][64];
    int r0 = blockIdx.x * 64;
    int t = threadIdx.x;  // 256 threads
    for (int i = t; i < 4096; i += 256) Ws[i >> 6][i & 63] = W[i];
    for (int i = t; i < 4096; i += 256) {
        int r = i >> 6;
        As[r][i & 63] = (r0 + r < n) ? A[(size_t)(r0 + r) * 64 + (i & 63)] : 0.f;
    }
    __syncthreads();
    int c = t & 63, ty = t >> 6;
    for (int i = 0; i < 16; i++) {
        int r = ty * 16 + i;
        float acc = 0.f;
#pragma unroll
        for (int kk = 0; kk < 64; kk++) acc += As[r][kk] * Ws[kk][c];
        if (r0 + r < n) C[(size_t)(r0 + r) * 64 + c] = acc;
    }
}

// out[i][:] = xw[i][:] * dis2[i] + b[:]   (self-loop message + bias)
__global__ void k_selfinit(const float4* __restrict__ xw4, const float* __restrict__ dis2,
                           const float4* __restrict__ b4, float4* __restrict__ out, int n) {
    int idx = blockIdx.x * blockDim.x + threadIdx.x;
    if (idx >= n * 16) return;
    int i = idx >> 4, c = idx & 15;
    float d = dis2[i];
    float4 v = xw4[idx];
    float4 bb = b4[c];
    out[idx] = make_float4(v.x * d + bb.x, v.y * d + bb.y, v.z * d + bb.z, v.w * d + bb.w);
}

// agg[dst] += xw[src] * enorm  — 16 float4 chunks per edge, grid-stride
__global__ void k_edge_agg(const float4* __restrict__ xw4, float* __restrict__ out,
                           const int* __restrict__ src, const int* __restrict__ dst,
                           const float* __restrict__ enorm,
                           const int* m_ptr, int m_static) {
    int m = m_ptr ? *m_ptr : m_static;
    int total = m * 16;
    for (int idx = blockIdx.x * blockDim.x + threadIdx.x; idx < total;
         idx += gridDim.x * blockDim.x) {
        int e = idx >> 4, c = idx & 15;
        float w = enorm[e];
        float4 v = xw4[src[e] * 16 + c];
        float* o = out + ((size_t)dst[e] * 64 + c * 4);
        atomicAdd(o + 0, v.x * w);
        atomicAdd(o + 1, v.y * w);
        atomicAdd(o + 2, v.z * w);
        atomicAdd(o + 3, v.w * w);
    }
}

__global__ void k_relu(float* h, int n64) {
    int i = blockIdx.x * blockDim.x + threadIdx.x;
    if (i < n64) h[i] = fmaxf(h[i], 0.f);
}

// sxw[i] = dot(h[i], Wp)  — one warp per node
__global__ void k_score_xw(const float* __restrict__ h, const float* __restrict__ Wp,
                           float* __restrict__ sxw, int n) {
    int gthread = blockIdx.x * blockDim.x + threadIdx.x;
    int warp = gthread >> 5;
    int lane = threadIdx.x & 31;
    if (warp >= n) return;
    float acc = h[(size_t)warp * 64 + lane] * Wp[lane] +
                h[(size_t)warp * 64 + lane + 32] * Wp[lane + 32];
#pragma unroll
    for (int o = 16; o > 0; o >>= 1) acc += __shfl_xor_sync(0xffffffffu, acc, o);
    if (lane == 0) sxw[warp] = acc;
}

__global__ void k_score_init(const float* __restrict__ sxw, const float* __restrict__ dis2,
                             const float* __restrict__ bp, float* score, int n) {
    int i = blockIdx.x * blockDim.x + threadIdx.x;
    if (i < n) score[i] = sxw[i] * dis2[i] + bp[0];
}

__global__ void k_score_agg(float* __restrict__ score, const float* __restrict__ sxw,
                            const int* __restrict__ src, const int* __restrict__ dst,
                            const float* __restrict__ enorm,
                            const int* m_ptr, int m_static) {
    int m = m_ptr ? *m_ptr : m_static;
    for (int e = blockIdx.x * blockDim.x + threadIdx.x; e < m;
         e += gridDim.x * blockDim.x)
        atomicAdd(&score[dst[e]], sxw[src[e]] * enorm[e]);
}

// Per-graph top-k: bitonic sort of (descending score, ascending index) keys.
__global__ void k_topk(const float* __restrict__ score, int n_cur, int k,
                       int* __restrict__ newidx, int* __restrict__ perm,
                       float* __restrict__ gate) {
    __shared__ unsigned long long keys[1024];
    int b = blockIdx.x;
    int base = b * n_cur;
    for (int j = threadIdx.x; j < 1024; j += blockDim.x) {
        unsigned long long kk;
        if (j < n_cur) {
            unsigned int u = __float_as_uint(score[base + j]);
            u ^= (u >> 31) ? 0xFFFFFFFFu : 0x80000000u;  // ascending-orderable
            unsigned int hi = ~u;                        // descending score
            kk = ((unsigned long long)hi << 32) | (unsigned int)j;
            newidx[base + j] = -1;
        } else {
            kk = 0xFFFFFFFFFFFFFFFFull;  // sink padding to the end
        }
        keys[j] = kk;
    }
    __syncthreads();
    for (int size = 2; size <= 1024; size <<= 1) {
        for (int stride = size >> 1; stride > 0; stride >>= 1) {
            int t = threadIdx.x;  // blockDim == 512 covers all pairs
            int pos = 2 * t - (t & (stride - 1));
            int q = pos + stride;
            bool up = ((pos & size) == 0);
            unsigned long long a = keys[pos], c = keys[q];
            if ((a > c) == up) { keys[pos] = c; keys[q] = a; }
            __syncthreads();
        }
    }
    for (int j = threadIdx.x; j < k; j += blockDim.x) {
        int oldloc = (int)(keys[j] & 0xFFFFFFFFull);
        int og = base + oldloc;
        int ng = b * k + j;
        newidx[og] = ng;
        perm[ng] = og;
        gate[ng] = tanhf(score[og]);
    }
}

// pooled[nn][:] = h[perm[nn]][:] * gate[nn]
__global__ void k_gather(const float4* __restrict__ h4, const int* __restrict__ perm,
                         const float* __restrict__ gate, float4* __restrict__ out,
                         int n_new) {
    int idx = blockIdx.x * blockDim.x + threadIdx.x;
    if (idx >= n_new * 16) return;
    int nn = idx >> 4, c = idx & 15;
    float g = gate[nn];
    float4 v = h4[(size_t)perm[nn] * 16 + c];
    out[idx] = make_float4(v.x * g, v.y * g, v.z * g, v.w * g);
}

// r[b][0:64] = max over k rows, r[b][64:128] = mean
__global__ void k_readout(const float* __restrict__ h, int k, float* __restrict__ r) {
    __shared__ float smax[256], ssum[256];
    int b = blockIdx.x, t = threadIdx.x;
    int f = t & 63, rq = t >> 6;
    float mx = -3.402823466e+38f, sm = 0.f;
    for (int row = rq; row < k; row += 4) {
        float v = h[((size_t)b * k + row) * 64 + f];
        mx = fmaxf(mx, v);
        sm += v;
    }
    smax[t] = mx;
    ssum[t] = sm;
    __syncthreads();
    if (t < 64) {
        float m2 = fmaxf(fmaxf(smax[t], smax[t + 64]), fmaxf(smax[t + 128], smax[t + 192]));
        float s2 = ssum[t] + ssum[t + 64] + ssum[t + 128] + ssum[t + 192];
        r[b * 128 + f] = m2;
        r[b * 128 + 64 + f] = s2 / (float)k;
    }
}

__global__ void k_compact(const int* __restrict__ src, const int* __restrict__ dst,
                          const int* m_ptr, int m_static, const int* __restrict__ newidx,
                          int* __restrict__ src_out, int* __restrict__ dst_out,
                          int* __restrict__ mcnt) {
    int m = m_ptr ? *m_ptr : m_static;
    for (int e = blockIdx.x * blockDim.x + threadIdx.x; e < m;
         e += gridDim.x * blockDim.x) {
        int ns = newidx[src[e]];
        int nd = newidx[dst[e]];
        if (ns >= 0 && nd >= 0) {
            int p = atomicAdd(mcnt, 1);
            src_out[p] = ns;
            dst_out[p] = nd;
        }
    }
}

// Final MLP + log_softmax; one block per graph, 64 threads.
__global__ void k_mlp(const float* __restrict__ r1, const float* __restrict__ r2,
                      const float* __restrict__ r3,
                      const float* __restrict__ L1w, const float* __restrict__ L1b,
                      const float* __restrict__ L2w, const float* __restrict__ L2b,
                      const float* __restrict__ L3w, const float* __restrict__ L3b,
                      float* __restrict__ out) {
    __shared__ float zs[128], h1[64], h2[32], os[10];
    __shared__ float lse;
    int b = blockIdx.x, t = threadIdx.x;
    zs[t] = r1[b * 128 + t] + r2[b * 128 + t] + r3[b * 128 + t];
    zs[t + 64] = r1[b * 128 + 64 + t] + r2[b * 128 + 64 + t] + r3[b * 128 + 64 + t];
    __syncthreads();
    {
        float acc = L1b[t];
        for (int j = 0; j < 128; j++) acc += zs[j] * L1w[j * 64 + t];
        h1[t] = fmaxf(acc, 0.f);
    }
    __syncthreads();
    if (t < 32) {
        float a = L2b[t];
        for (int j = 0; j < 64; j++) a += h1[j] * L2w[j * 32 + t];
        h2[t] = fmaxf(a, 0.f);
    }
    __syncthreads();
    if (t < 10) {
        float a = L3b[t];
        for (int j = 0; j < 32; j++) a += h2[j] * L3w[j * 10 + t];
        os[t] = a;
    }
    __syncthreads();
    if (t == 0) {
        float mx = os[0];
        for (int j = 1; j < 10; j++) mx = fmaxf(mx, os[j]);
        float s = 0.f;
        for (int j = 0; j < 10; j++) s += expf(os[j] - mx);
        lse = mx + logf(s);
    }
    __syncthreads();
    if (t < 10) out[b * 10 + t] = os[t] - lse;
}

// ---------------- host orchestration ----------------

static void run_stage(const float* h_in, int n_cur, int n_tot,
                      const int* es, const int* ed, const int* m_ptr,
                      const float* W, const float* b, const float* Wp, const float* bp,
                      float* conv, float* pool, int k, float* rbuf,
                      int* es_out, int* ed_out, int* mcnt_out,
                      float* deg, float* dis, float* dis2, float* xw,
                      float* sxw, float* score, float* gate, float* enorm,
                      int* newidx, int* perm) {
    int n_new = BGRAPHS * k;
    k_stage_init<<<(n_tot + 255) / 256, 256>>>(deg, n_tot, mcnt_out);
    k_deg_acc<<<EGRID, ETHREADS>>>(ed, m_ptr, EMAX, deg);
    k_dis<<<(n_tot + 255) / 256, 256>>>(deg, dis, dis2, n_tot);
    k_gemm64<<<(n_tot + 63) / 64, 256>>>(h_in, W, xw, n_tot);
    k_selfinit<<<(n_tot * 16 + 255) / 256, 256>>>((const float4*)xw, dis2,
                                                  (const float4*)b, (float4*)conv, n_tot);
    k_enorm<<<EGRID, ETHREADS>>>(es, ed, m_ptr, EMAX, dis, enorm);
    k_edge_agg<<<EGRID * 2, ETHREADS>>>((const float4*)xw, conv, es, ed, enorm,
                                        m_ptr, EMAX);
    k_relu<<<(n_tot * 64 + 255) / 256, 256>>>(conv, n_tot * 64);
    // pooling score (GCN conv with Wp: 64 -> 1)
    k_score_xw<<<(n_tot * 32 + 255) / 256, 256>>>(conv, Wp, sxw, n_tot);
    k_score_init<<<(n_tot + 255) / 256, 256>>>(sxw, dis2, bp, score, n_tot);
    k_score_agg<<<EGRID, ETHREADS>>>(score, sxw, es, ed, enorm, m_ptr, EMAX);
    k_topk<<<BGRAPHS, 512>>>(score, n_cur, k, newidx, perm, gate);
    k_gather<<<(n_new * 16 + 255) / 256, 256>>>((const float4*)conv, perm, gate,
                                                (float4*)pool, n_new);
    k_readout<<<BGRAPHS, 256>>>(pool, k, rbuf);
    if (es_out)
        k_compact<<<EGRID, ETHREADS>>>(es, ed, m_ptr, EMAX, newidx, es_out, ed_out,
                                       mcnt_out);
}

extern "C" void kernel_launch(void* const* d_in, const int* in_sizes, int n_in,
                              void* d_out, int out_size) {
    const float* x    = (const float*)d_in[0];
    const int* esrc   = (const int*)d_in[1];
    const int* edst   = (const int*)d_in[2];
    const float* W1   = (const float*)d_in[3];
    const float* b1   = (const float*)d_in[4];
    const float* Wp1  = (const float*)d_in[5];
    const float* bp1  = (const float*)d_in[6];
    const float* W2   = (const float*)d_in[7];
    const float* b2   = (const float*)d_in[8];
    const float* Wp2  = (const float*)d_in[9];
    const float* bp2  = (const float*)d_in[10];
    const float* W3   = (const float*)d_in[11];
    const float* b3   = (const float*)d_in[12];
    const float* Wp3  = (const float*)d_in[13];
    const float* bp3  = (const float*)d_in[14];
    const float* L1w  = (const float*)d_in[15];
    const float* L1b  = (const float*)d_in[16];
    const float* L2w  = (const float*)d_in[17];
    const float* L2b  = (const float*)d_in[18];
    const float* L3w  = (const float*)d_in[19];
    const float* L3b  = (const float*)d_in[20];
    float* out = (float*)d_out;

    float *pA, *pB, *pxw, *pdeg, *pdis, *pdis2, *psxw, *pscore, *pgate, *penorm;
    float *pr1, *pr2, *pr3;
    int *pes1, *ped1, *pes2, *ped2, *pnew, *pperm, *pmcnt;
    cudaGetSymbolAddress((void**)&pA, g_A);
    cudaGetSymbolAddress((void**)&pB, g_B);
    cudaGetSymbolAddress((void**)&pxw, g_xw);
    cudaGetSymbolAddress((void**)&pdeg, g_deg);
    cudaGetSymbolAddress((void**)&pdis, g_dis);
    cudaGetSymbolAddress((void**)&pdis2, g_dis2);
    cudaGetSymbolAddress((void**)&psxw, g_sxw);
    cudaGetSymbolAddress((void**)&pscore, g_score);
    cudaGetSymbolAddress((void**)&pgate, g_gate);
    cudaGetSymbolAddress((void**)&penorm, g_enorm);
    cudaGetSymbolAddress((void**)&pes1, g_es1);
    cudaGetSymbolAddress((void**)&ped1, g_ed1);
    cudaGetSymbolAddress((void**)&pes2, g_es2);
    cudaGetSymbolAddress((void**)&ped2, g_ed2);
    cudaGetSymbolAddress((void**)&pnew, g_newidx);
    cudaGetSymbolAddress((void**)&pperm, g_perm);
    cudaGetSymbolAddress((void**)&pmcnt, g_mcnt);
    cudaGetSymbolAddress((void**)&pr1, g_r1);
    cudaGetSymbolAddress((void**)&pr2, g_r2);
    cudaGetSymbolAddress((void**)&pr3, g_r3);

    // Stage 1: input x, all E edges (static count)
    run_stage(x, N0, NT1, esrc, edst, nullptr,
              W1, b1, Wp1, bp1, pA, pB, K1, pr1,
              pes1, ped1, pmcnt + 0,
              pdeg, pdis, pdis2, pxw, psxw, pscore, pgate, penorm, pnew, pperm);
    // Stage 2: input pooled (g_B), compacted edges 1, count in g_mcnt[0]
    run_stage(pB, K1, NT2, pes1, ped1, pmcnt + 0,
              W2, b2, Wp2, bp2, pA, pB, K2, pr2,
              pes2, ped2, pmcnt + 1,
              pdeg, pdis, pdis2, pxw, psxw, pscore, pgate, penorm, pnew, pperm);
    // Stage 3: no edge output needed
    run_stage(pB, K2, NT3, pes2, ped2, pmcnt + 1,
              W3, b3, Wp3, bp3, pA, pB, K3, pr3,
              nullptr, nullptr, nullptr,
              pdeg, pdis, pdis2, pxw, psxw, pscore, pgate, penorm, pnew, pperm);

    k_mlp<<<BGRAPHS, 64>>>(pr1, pr2, pr3, L1w, L1b, L2w, L2b, L3w, L3b, out);
}

// round 2
// speedup vs baseline: 1.7578x; 1.7578x over previous
#include <cuda_runtime.h>
#include <math.h>

// ---------------- problem constants ----------------
#define BGRAPHS 128
#define N0      1024
#define EMAX    1048576
#define NT1     (BGRAPHS * N0)        // 131072
#define K1      820
#define NT2     (BGRAPHS * K1)        // 104960
#define K2      656
#define NT3     (BGRAPHS * K2)        // 83968
#define K3      525
#define NHID    64
#define NCLS    10

#define EGRID    1024
#define ETHREADS 256

// ---------------- device scratch ----------------
__device__ float g_A[NT1 * 64];       // conv output h
__device__ float g_B[NT1 * 64];       // pooled features (ping-pong)
__device__ float g_xw[NT1 * 64];      // GEMM output, pre-scaled by dis[row]
__device__ float g_dis[NT1];
__device__ float g_sxws[NT1];         // dis[i] * (h[i]·Wp)
__device__ float g_score[NT1];
__device__ float g_gate[NT1];
__device__ int   g_cntA[NT1], g_cntB[NT1];
__device__ int   g_rowptr[NT1], g_cursor[NT1];
__device__ int   g_csr[EMAX];
__device__ int   g_chsum[512], g_choff[512];
__device__ int   g_es1[EMAX], g_ed1[EMAX];
__device__ int   g_es2[EMAX], g_ed2[EMAX];
__device__ int   g_newidx[NT1];
__device__ int   g_perm[NT1];
__device__ int   g_mcnt[2];
__device__ float g_r1[BGRAPHS * 128], g_r2[BGRAPHS * 128], g_r3[BGRAPHS * 128];

// ---------------- CSR build ----------------

__global__ void k_hist(const int* __restrict__ dst, const int* m_ptr, int m_static,
                       int* __restrict__ cnt) {
    int m = m_ptr ? *m_ptr : m_static;
    for (int e = blockIdx.x * blockDim.x + threadIdx.x; e < m;
         e += gridDim.x * blockDim.x)
        atomicAdd(&cnt[dst[e]], 1);
}

__global__ void k_chunksum(const int* __restrict__ cnt, int n, int* __restrict__ chsum) {
    __shared__ int s[256];
    int b = blockIdx.x, t = threadIdx.x;
    int i = b * 256 + t;
    s[t] = (i < n) ? cnt[i] : 0;
    __syncthreads();
    for (int off = 128; off > 0; off >>= 1) {
        if (t < off) s[t] += s[t + off];
        __syncthreads();
    }
    if (t == 0) chsum[b] = s[0];
}

__global__ void k_scanchunks(const int* __restrict__ chsum, int* __restrict__ choff,
                             int nch) {
    __shared__ int s[512];
    int t = threadIdx.x;
    int v0 = (t < nch) ? chsum[t] : 0;
    s[t] = v0;
    __syncthreads();
    for (int off = 1; off < 512; off <<= 1) {
        int v = (t >= off) ? s[t - off] : 0;
        __syncthreads();
        s[t] += v;
        __syncthreads();
    }
    if (t < nch) choff[t] = s[t] - v0;  // exclusive
}

__global__ void k_scanwrite(const int* __restrict__ cnt, const int* __restrict__ choff,
                            int n, int* __restrict__ rowptr, int* __restrict__ cursor,
                            float* __restrict__ dis) {
    __shared__ int s[256];
    int b = blockIdx.x, t = threadIdx.x, i = b * 256 + t;
    int c = (i < n) ? cnt[i] : 0;
    s[t] = c;
    __syncthreads();
    for (int off = 1; off < 256; off <<= 1) {
        int v = (t >= off) ? s[t - off] : 0;
        __syncthreads();
        s[t] += v;
        __syncthreads();
    }
    if (i < n) {
        int ex = choff[b] + s[t] - c;
        rowptr[i] = ex;
        cursor[i] = ex;
        dis[i] = rsqrtf((float)c + 1.0f);
    }
}

__global__ void k_scatter(const int* __restrict__ src, const int* __restrict__ dst,
                          const int* m_ptr, int m_static,
                          int* __restrict__ cursor, int* __restrict__ csr) {
    int m = m_ptr ? *m_ptr : m_static;
    for (int e = blockIdx.x * blockDim.x + threadIdx.x; e < m;
         e += gridDim.x * blockDim.x) {
        int p = atomicAdd(&cursor[dst[e]], 1);
        csr[p] = src[e];
    }
}

// ---------------- GEMM: C[r] = (A @ W)[r] * scale[r], n % 64 == 0 ----------------
__global__ void __launch_bounds__(256) k_gemm64s(
    const float* __restrict__ A, const float* __restrict__ W,
    const float* __restrict__ scale, float* __restrict__ C) {
    __shared__ float As[64][65];
    __shared__ float Ws[64][64];  // [k][c]
    int t = threadIdx.x;
    int r0 = blockIdx.x * 64;
    for (int i = t; i < 4096; i += 256) Ws[i >> 6][i & 63] = W[i];
    const float4* A4 = (const float4*)(A + (size_t)r0 * 64);
    for (int i = t; i < 1024; i += 256) {
        int r = i >> 4, c4 = i & 15;
        float4 v = A4[i];
        As[r][c4 * 4 + 0] = v.x;
        As[r][c4 * 4 + 1] = v.y;
        As[r][c4 * 4 + 2] = v.z;
        As[r][c4 * 4 + 3] = v.w;
    }
    __syncthreads();
    int tx = t & 15, ty = t >> 4;
    float acc[4][4] = {};
#pragma unroll 16
    for (int k = 0; k < 64; k++) {
        float4 w = *(const float4*)&Ws[k][tx * 4];
        float a0 = As[ty * 4 + 0][k];
        float a1 = As[ty * 4 + 1][k];
        float a2 = As[ty * 4 + 2][k];
        float a3 = As[ty * 4 + 3][k];
        acc[0][0] += a0 * w.x; acc[0][1] += a0 * w.y; acc[0][2] += a0 * w.z; acc[0][3] += a0 * w.w;
        acc[1][0] += a1 * w.x; acc[1][1] += a1 * w.y; acc[1][2] += a1 * w.z; acc[1][3] += a1 * w.w;
        acc[2][0] += a2 * w.x; acc[2][1] += a2 * w.y; acc[2][2] += a2 * w.z; acc[2][3] += a2 * w.w;
        acc[3][0] += a3 * w.x; acc[3][1] += a3 * w.y; acc[3][2] += a3 * w.z; acc[3][3] += a3 * w.w;
    }
#pragma unroll
    for (int i = 0; i < 4; i++) {
        int r = r0 + ty * 4 + i;
        float s = scale[r];
        float4 o = make_float4(acc[i][0] * s, acc[i][1] * s, acc[i][2] * s, acc[i][3] * s);
        *(float4*)&C[(size_t)r * 64 + tx * 4] = o;
    }
}

// ---------------- fused aggregation: conv + bias + relu + score projection ------
// one warp per node; lane handles features (2*lane, 2*lane+1)
__global__ void k_agg(const float2* __restrict__ xws2, const int* __restrict__ rowptr,
                      const int* __restrict__ cnt, const float* __restrict__ dis,
                      const int* __restrict__ csr,
                      const float* __restrict__ b, const float* __restrict__ Wp,
                      float2* __restrict__ h2, float* __restrict__ sxws, int n) {
    int w = (blockIdx.x * blockDim.x + threadIdx.x) >> 5;
    if (w >= n) return;
    int lane = threadIdx.x & 31;
    int start = rowptr[w], dc = cnt[w];
    float2 acc = xws2[(size_t)w * 32 + lane];  // self message (pre-scaled)
    for (int base = 0; base < dc; base += 32) {
        int rem = dc - base;
        int s = (lane < rem) ? csr[start + base + lane] : 0;
        int lim = rem < 32 ? rem : 32;
        for (int j = 0; j < lim; j++) {
            int sj = __shfl_sync(0xffffffffu, s, j);
            float2 v = xws2[(size_t)sj * 32 + lane];
            acc.x += v.x;
            acc.y += v.y;
        }
    }
    float di = dis[w];
    float2 o;
    o.x = fmaxf(acc.x * di + b[2 * lane], 0.f);
    o.y = fmaxf(acc.y * di + b[2 * lane + 1], 0.f);
    h2[(size_t)w * 32 + lane] = o;
    float sa = o.x * Wp[2 * lane] + o.y * Wp[2 * lane + 1];
#pragma unroll
    for (int off = 16; off > 0; off >>= 1) sa += __shfl_xor_sync(0xffffffffu, sa, off);
    if (lane == 0) sxws[w] = sa * di;
}

// score[i] = bp + dis[i] * (sxws[i] + sum_{s in N(i)} sxws[s])
__global__ void k_score(const float* __restrict__ sxws, const int* __restrict__ rowptr,
                        const int* __restrict__ cnt, const float* __restrict__ dis,
                        const int* __restrict__ csr, const float* __restrict__ bp,
                        float* __restrict__ score, int n) {
    int i = blockIdx.x * blockDim.x + threadIdx.x;
    if (i >= n) return;
    int start = rowptr[i], dc = cnt[i];
    float acc = sxws[i];
    for (int j = 0; j < dc; j++) acc += sxws[csr[start + j]];
    score[i] = bp[0] + dis[i] * acc;
}

// ---------------- top-k (bitonic sort per graph) ----------------
__global__ void k_topk(const float* __restrict__ score, int n_cur, int k,
                       int* __restrict__ newidx, int* __restrict__ perm,
                       float* __restrict__ gate) {
    __shared__ unsigned long long keys[1024];
    int b = blockIdx.x;
    int base = b * n_cur;
    for (int j = threadIdx.x; j < 1024; j += blockDim.x) {
        unsigned long long kk;
        if (j < n_cur) {
            unsigned int u = __float_as_uint(score[base + j]);
            u ^= (u >> 31) ? 0xFFFFFFFFu : 0x80000000u;
            unsigned int hi = ~u;
            kk = ((unsigned long long)hi << 32) | (unsigned int)j;
            newidx[base + j] = -1;
        } else {
            kk = 0xFFFFFFFFFFFFFFFFull;
        }
        keys[j] = kk;
    }
    __syncthreads();
    for (int size = 2; size <= 1024; size <<= 1) {
        for (int stride = size >> 1; stride > 0; stride >>= 1) {
            int t = threadIdx.x;
            int pos = 2 * t - (t & (stride - 1));
            int q = pos + stride;
            bool up = ((pos & size) == 0);
            unsigned long long a = keys[pos], c = keys[q];
            if ((a > c) == up) { keys[pos] = c; keys[q] = a; }
            __syncthreads();
        }
    }
    for (int j = threadIdx.x; j < k; j += blockDim.x) {
        int oldloc = (int)(keys[j] & 0xFFFFFFFFull);
        int og = base + oldloc;
        int ng = b * k + j;
        newidx[og] = ng;
        perm[ng] = og;
        gate[ng] = tanhf(score[og]);
    }
}

__global__ void k_gather(const float4* __restrict__ h4, const int* __restrict__ perm,
                         const float* __restrict__ gate, float4* __restrict__ out,
                         int n_new) {
    int idx = blockIdx.x * blockDim.x + threadIdx.x;
    if (idx >= n_new * 16) return;
    int nn = idx >> 4, c = idx & 15;
    float g = gate[nn];
    float4 v = h4[(size_t)perm[nn] * 16 + c];
    out[idx] = make_float4(v.x * g, v.y * g, v.z * g, v.w * g);
}

__global__ void k_readout(const float* __restrict__ h, int k, float* __restrict__ r) {
    __shared__ float smax[256], ssum[256];
    int b = blockIdx.x, t = threadIdx.x;
    int f = t & 63, rq = t >> 6;
    float mx = -3.402823466e+38f, sm = 0.f;
    for (int row = rq; row < k; row += 4) {
        float v = h[((size_t)b * k + row) * 64 + f];
        mx = fmaxf(mx, v);
        sm += v;
    }
    smax[t] = mx;
    ssum[t] = sm;
    __syncthreads();
    if (t < 64) {
        float m2 = fmaxf(fmaxf(smax[t], smax[t + 64]), fmaxf(smax[t + 128], smax[t + 192]));
        float s2 = ssum[t] + ssum[t + 64] + ssum[t + 128] + ssum[t + 192];
        r[b * 128 + f] = m2;
        r[b * 128 + 64 + f] = s2 / (float)k;
    }
}

// compact edges into new id space AND histogram next stage's in-degrees
__global__ void k_compact(const int* __restrict__ src, const int* __restrict__ dst,
                          const int* m_ptr, int m_static, const int* __restrict__ newidx,
                          int* __restrict__ src_out, int* __restrict__ dst_out,
                          int* __restrict__ mcnt, int* __restrict__ cnt_next) {
    int m = m_ptr ? *m_ptr : m_static;
    for (int e = blockIdx.x * blockDim.x + threadIdx.x; e < m;
         e += gridDim.x * blockDim.x) {
        int ns = newidx[src[e]];
        int nd = newidx[dst[e]];
        if (ns >= 0 && nd >= 0) {
            int p = atomicAdd(mcnt, 1);
            src_out[p] = ns;
            dst_out[p] = nd;
            atomicAdd(&cnt_next[nd], 1);
        }
    }
}

// ---------------- final MLP ----------------
__global__ void k_mlp(const float* __restrict__ r1, const float* __restrict__ r2,
                      const float* __restrict__ r3,
                      const float* __restrict__ L1w, const float* __restrict__ L1b,
                      const float* __restrict__ L2w, const float* __restrict__ L2b,
                      const float* __restrict__ L3w, const float* __restrict__ L3b,
                      float* __restrict__ out) {
    __shared__ float zs[128], h1[64], h2[32], os[10];
    __shared__ float lse;
    int b = blockIdx.x, t = threadIdx.x;
    zs[t] = r1[b * 128 + t] + r2[b * 128 + t] + r3[b * 128 + t];
    zs[t + 64] = r1[b * 128 + 64 + t] + r2[b * 128 + 64 + t] + r3[b * 128 + 64 + t];
    __syncthreads();
    {
        float acc = L1b[t];
        for (int j = 0; j < 128; j++) acc += zs[j] * L1w[j * 64 + t];
        h1[t] = fmaxf(acc, 0.f);
    }
    __syncthreads();
    if (t < 32) {
        float a = L2b[t];
        for (int j = 0; j < 64; j++) a += h1[j] * L2w[j * 32 + t];
        h2[t] = fmaxf(a, 0.f);
    }
    __syncthreads();
    if (t < 10) {
        float a = L3b[t];
        for (int j = 0; j < 32; j++) a += h2[j] * L3w[j * 10 + t];
        os[t] = a;
    }
    __syncthreads();
    if (t == 0) {
        float mx = os[0];
        for (int j = 1; j < 10; j++) mx = fmaxf(mx, os[j]);
        float s = 0.f;
        for (int j = 0; j < 10; j++) s += expf(os[j] - mx);
        lse = mx + logf(s);
    }
    __syncthreads();
    if (t < 10) out[b * 10 + t] = os[t] - lse;
}

// ---------------- host orchestration ----------------

struct Ptrs {
    float *A, *B, *xw, *dis, *sxws, *score, *gate;
    float *r1, *r2, *r3;
    int *cntA, *cntB, *rowptr, *cursor, *csr, *chsum, *choff;
    int *es1, *ed1, *es2, *ed2, *newidx, *perm, *mcnt;
};

static void run_stage(const Ptrs& p, const float* h_in, int n_cur, int n_tot,
                      const int* es, const int* ed, const int* m_ptr,
                      int* cnt, int* cnt_next,
                      const float* W, const float* b, const float* Wp, const float* bp,
                      int k, float* rbuf,
                      int* es_out, int* ed_out, int* mcnt_out, bool do_hist) {
    int nch = (n_tot + 255) / 256;
    int n_new = BGRAPHS * k;
    if (do_hist) k_hist<<<EGRID, ETHREADS>>>(ed, m_ptr, EMAX, cnt);
    k_chunksum<<<nch, 256>>>(cnt, n_tot, p.chsum);
    k_scanchunks<<<1, 512>>>(p.chsum, p.choff, nch);
    k_scanwrite<<<nch, 256>>>(cnt, p.choff, n_tot, p.rowptr, p.cursor, p.dis);
    k_scatter<<<EGRID, ETHREADS>>>(es, ed, m_ptr, EMAX, p.cursor, p.csr);
    k_gemm64s<<<n_tot / 64, 256>>>(h_in, W, p.dis, p.xw);
    k_agg<<<n_tot / 8, 256>>>((const float2*)p.xw, p.rowptr, cnt, p.dis, p.csr,
                              b, Wp, (float2*)p.A, p.sxws, n_tot);
    k_score<<<(n_tot + 255) / 256, 256>>>(p.sxws, p.rowptr, cnt, p.dis, p.csr, bp,
                                          p.score, n_tot);
    k_topk<<<BGRAPHS, 512>>>(p.score, n_cur, k, p.newidx, p.perm, p.gate);
    k_gather<<<(n_new * 16 + 255) / 256, 256>>>((const float4*)p.A, p.perm, p.gate,
                                                (float4*)p.B, n_new);
    k_readout<<<BGRAPHS, 256>>>(p.B, k, rbuf);
    if (es_out)
        k_compact<<<EGRID, ETHREADS>>>(es, ed, m_ptr, EMAX, p.newidx, es_out, ed_out,
                                       mcnt_out, cnt_next);
}

extern "C" void kernel_launch(void* const* d_in, const int* in_sizes, int n_in,
                              void* d_out, int out_size) {
    const float* x   = (const float*)d_in[0];
    const int* esrc  = (const int*)d_in[1];
    const int* edst  = (const int*)d_in[2];
    const float* W1  = (const float*)d_in[3];
    const float* b1  = (const float*)d_in[4];
    const float* Wp1 = (const float*)d_in[5];
    const float* bp1 = (const float*)d_in[6];
    const float* W2  = (const float*)d_in[7];
    const float* b2  = (const float*)d_in[8];
    const float* Wp2 = (const float*)d_in[9];
    const float* bp2 = (const float*)d_in[10];
    const float* W3  = (const float*)d_in[11];
    const float* b3  = (const float*)d_in[12];
    const float* Wp3 = (const float*)d_in[13];
    const float* bp3 = (const float*)d_in[14];
    const float* L1w = (const float*)d_in[15];
    const float* L1b = (const float*)d_in[16];
    const float* L2w = (const float*)d_in[17];
    const float* L2b = (const float*)d_in[18];
    const float* L3w = (const float*)d_in[19];
    const float* L3b = (const float*)d_in[20];
    float* out = (float*)d_out;

    Ptrs p;
    cudaGetSymbolAddress((void**)&p.A, g_A);
    cudaGetSymbolAddress((void**)&p.B, g_B);
    cudaGetSymbolAddress((void**)&p.xw, g_xw);
    cudaGetSymbolAddress((void**)&p.dis, g_dis);
    cudaGetSymbolAddress((void**)&p.sxws, g_sxws);
    cudaGetSymbolAddress((void**)&p.score, g_score);
    cudaGetSymbolAddress((void**)&p.gate, g_gate);
    cudaGetSymbolAddress((void**)&p.cntA, g_cntA);
    cudaGetSymbolAddress((void**)&p.cntB, g_cntB);
    cudaGetSymbolAddress((void**)&p.rowptr, g_rowptr);
    cudaGetSymbolAddress((void**)&p.cursor, g_cursor);
    cudaGetSymbolAddress((void**)&p.csr, g_csr);
    cudaGetSymbolAddress((void**)&p.chsum, g_chsum);
    cudaGetSymbolAddress((void**)&p.choff, g_choff);
    cudaGetSymbolAddress((void**)&p.es1, g_es1);
    cudaGetSymbolAddress((void**)&p.ed1, g_ed1);
    cudaGetSymbolAddress((void**)&p.es2, g_es2);
    cudaGetSymbolAddress((void**)&p.ed2, g_ed2);
    cudaGetSymbolAddress((void**)&p.newidx, g_newidx);
    cudaGetSymbolAddress((void**)&p.perm, g_perm);
    cudaGetSymbolAddress((void**)&p.mcnt, g_mcnt);
    cudaGetSymbolAddress((void**)&p.r1, g_r1);
    cudaGetSymbolAddress((void**)&p.r2, g_r2);
    cudaGetSymbolAddress((void**)&p.r3, g_r3);

    cudaMemsetAsync(p.cntA, 0, NT1 * sizeof(int), 0);
    cudaMemsetAsync(p.cntB, 0, NT2 * sizeof(int), 0);
    cudaMemsetAsync(p.mcnt, 0, 2 * sizeof(int), 0);

    // Stage 1: static E edges; hist needed; compact hists cntB for stage 2
    run_stage(p, x, N0, NT1, esrc, edst, nullptr, p.cntA, p.cntB,
              W1, b1, Wp1, bp1, K1, p.r1, p.es1, p.ed1, p.mcnt + 0, true);

    // Stage 2: cntB already histogrammed by stage-1 compact; zero cntA for stage 3
    cudaMemsetAsync(p.cntA, 0, NT3 * sizeof(int), 0);
    run_stage(p, p.B, K1, NT2, p.es1, p.ed1, p.mcnt + 0, p.cntB, p.cntA,
              W2, b2, Wp2, bp2, K2, p.r2, p.es2, p.ed2, p.mcnt + 1, false);

    // Stage 3: cntA histogrammed by stage-2 compact; no next stage
    run_stage(p, p.B, K2, NT3, p.es2, p.ed2, p.mcnt + 1, p.cntA, nullptr,
              W3, b3, Wp3, bp3, K3, p.r3, nullptr, nullptr, nullptr, false);

    k_mlp<<<BGRAPHS, 64>>>(p.r1, p.r2, p.r3, L1w, L1b, L2w, L2b, L3w, L3b, out);
}

// round 3
// speedup vs baseline: 2.1054x; 1.1978x over previous
#include <cuda_runtime.h>
#include <math.h>

// ---------------- problem constants ----------------
#define BGRAPHS 128
#define N0      1024
#define EPG     8192                  // edges per graph (E / B)
#define EMAX    1048576
#define NT1     (BGRAPHS * N0)        // 131072
#define K1      820
#define NT2     (BGRAPHS * K1)        // 104960
#define K2      656
#define NT3     (BGRAPHS * K2)        // 83968
#define K3      525

// ---------------- device scratch ----------------
__device__ float g_A[NT1 * 64];       // conv output h
__device__ float g_B[NT1 * 64];       // pooled features (ping-pong with A as gemm input)
__device__ float g_xw[NT1 * 64];      // GEMM output, pre-scaled by dis[row]
__device__ float g_disA[NT1], g_disB[NT1];
__device__ float g_sxws[NT1];         // dis[i] * (h[i]·Wp)
__device__ int   g_rpA[NT1], g_rpB[NT1];
__device__ int   g_cntA[NT1], g_cntB[NT1];
__device__ int   g_csrA[EMAX], g_csrB[EMAX];
__device__ float g_r1[BGRAPHS * 128], g_r2[BGRAPHS * 128], g_r3[BGRAPHS * 128];

// ---------------- stage-1 CSR build: one block per graph, all in smem ----------
__global__ void __launch_bounds__(512) k_csr0(
    const int* __restrict__ src, const int* __restrict__ dst,
    int* __restrict__ rowptr, int* __restrict__ cnt, float* __restrict__ dis,
    int* __restrict__ csr) {
    __shared__ int scnt[1024];
    __shared__ int sA[1024], sB[1024];
    __shared__ int scur[1024];
    int b = blockIdx.x, t = threadIdx.x;
    int ebase = b * EPG, nbase = b * N0;
    for (int i = t; i < 1024; i += 512) scnt[i] = 0;
    __syncthreads();
    for (int e = t; e < EPG; e += 512)
        atomicAdd(&scnt[dst[ebase + e] - nbase], 1);
    __syncthreads();
    for (int i = t; i < 1024; i += 512) sA[i] = scnt[i];
    __syncthreads();
    int* pin = sA; int* pout = sB;
    for (int off = 1; off < 1024; off <<= 1) {
        for (int i = t; i < 1024; i += 512)
            pout[i] = pin[i] + ((i >= off) ? pin[i - off] : 0);
        __syncthreads();
        int* tmp = pin; pin = pout; pout = tmp;
    }
    for (int i = t; i < 1024; i += 512) {
        int c = scnt[i];
        int ex = pin[i] - c;
        rowptr[nbase + i] = ebase + ex;
        cnt[nbase + i] = c;
        dis[nbase + i] = rsqrtf((float)c + 1.0f);
        scur[i] = ex;
    }
    __syncthreads();
    for (int e = t; e < EPG; e += 512) {
        int d = dst[ebase + e] - nbase;
        int p = atomicAdd(&scur[d], 1);
        csr[ebase + p] = src[ebase + e];
    }
}

// ---------------- GEMM: C[r] = (A @ W)[r] * scale[r], n % 64 == 0 ----------------
__global__ void __launch_bounds__(256) k_gemm64s(
    const float* __restrict__ A, const float* __restrict__ W,
    const float* __restrict__ scale, float* __restrict__ C) {
    __shared__ float As[64][65];
    __shared__ float Ws[64][64];
    int t = threadIdx.x;
    int r0 = blockIdx.x * 64;
    for (int i = t; i < 4096; i += 256) Ws[i >> 6][i & 63] = W[i];
    const float4* A4 = (const float4*)(A + (size_t)r0 * 64);
    for (int i = t; i < 1024; i += 256) {
        int r = i >> 4, c4 = i & 15;
        float4 v = A4[i];
        As[r][c4 * 4 + 0] = v.x;
        As[r][c4 * 4 + 1] = v.y;
        As[r][c4 * 4 + 2] = v.z;
        As[r][c4 * 4 + 3] = v.w;
    }
    __syncthreads();
    int tx = t & 15, ty = t >> 4;
    float acc[4][4] = {};
#pragma unroll 16
    for (int k = 0; k < 64; k++) {
        float4 w = *(const float4*)&Ws[k][tx * 4];
        float a0 = As[ty * 4 + 0][k];
        float a1 = As[ty * 4 + 1][k];
        float a2 = As[ty * 4 + 2][k];
        float a3 = As[ty * 4 + 3][k];
        acc[0][0] += a0 * w.x; acc[0][1] += a0 * w.y; acc[0][2] += a0 * w.z; acc[0][3] += a0 * w.w;
        acc[1][0] += a1 * w.x; acc[1][1] += a1 * w.y; acc[1][2] += a1 * w.z; acc[1][3] += a1 * w.w;
        acc[2][0] += a2 * w.x; acc[2][1] += a2 * w.y; acc[2][2] += a2 * w.z; acc[2][3] += a2 * w.w;
        acc[3][0] += a3 * w.x; acc[3][1] += a3 * w.y; acc[3][2] += a3 * w.z; acc[3][3] += a3 * w.w;
    }
#pragma unroll
    for (int i = 0; i < 4; i++) {
        int r = r0 + ty * 4 + i;
        float s = scale[r];
        *(float4*)&C[(size_t)r * 64 + tx * 4] =
            make_float4(acc[i][0] * s, acc[i][1] * s, acc[i][2] * s, acc[i][3] * s);
    }
}

// ---------------- fused aggregation: conv + bias + relu + score projection ------
// one warp per node; lane handles features (2*lane, 2*lane+1)
__global__ void k_agg(const float2* __restrict__ xws2, const int* __restrict__ rowptr,
                      const int* __restrict__ cnt, const float* __restrict__ dis,
                      const int* __restrict__ csr,
                      const float* __restrict__ b, const float* __restrict__ Wp,
                      float2* __restrict__ h2, float* __restrict__ sxws, int n) {
    int w = (blockIdx.x * blockDim.x + threadIdx.x) >> 5;
    if (w >= n) return;
    int lane = threadIdx.x & 31;
    int start = rowptr[w], dc = cnt[w];
    float2 acc = xws2[(size_t)w * 32 + lane];  // self message (pre-scaled by dis)
    for (int base = 0; base < dc; base += 32) {
        int rem = dc - base;
        int s = (lane < rem) ? csr[start + base + lane] : 0;
        int lim = rem < 32 ? rem : 32;
        for (int j = 0; j < lim; j++) {
            int sj = __shfl_sync(0xffffffffu, s, j);
            float2 v = xws2[(size_t)sj * 32 + lane];
            acc.x += v.x;
            acc.y += v.y;
        }
    }
    float di = dis[w];
    float2 o;
    o.x = fmaxf(acc.x * di + b[2 * lane], 0.f);
    o.y = fmaxf(acc.y * di + b[2 * lane + 1], 0.f);
    h2[(size_t)w * 32 + lane] = o;
    float sa = o.x * Wp[2 * lane] + o.y * Wp[2 * lane + 1];
#pragma unroll
    for (int off = 16; off > 0; off >>= 1) sa += __shfl_xor_sync(0xffffffffu, sa, off);
    if (lane == 0) sxws[w] = sa * di;
}

// ---------------- fused per-graph pool: score + topk + gather + readout + CSR filter
__global__ void __launch_bounds__(512) k_pool(
    const float* __restrict__ A, const float* __restrict__ sxws,
    const float* __restrict__ dis_o, const int* __restrict__ rp_o,
    const int* __restrict__ cnt_o, const int* __restrict__ csr_o,
    const float* __restrict__ bp, int n_cur, int k, int write_next,
    float* __restrict__ B, float* __restrict__ rbuf,
    int* __restrict__ rp_n, int* __restrict__ cnt_n, float* __restrict__ dis_n,
    int* __restrict__ csr_n) {
    __shared__ float sc[1024];
    __shared__ unsigned long long keys[1024];
    __shared__ int nidx[1024];
    __shared__ int sA[1024], sB[1024];
    __shared__ float rred[512];
    int b = blockIdx.x, t = threadIdx.x;
    int nbase = b * n_cur;
    float bp0 = bp[0];
    // 1. scores: bp + dis * (self + neighbor sum of sxws)
    for (int i = t; i < n_cur; i += 512) {
        int g = nbase + i;
        int st = rp_o[g], dc = cnt_o[g];
        float acc = sxws[g];
        for (int q = 0; q < dc; q++) acc += sxws[csr_o[st + q]];
        float s = bp0 + dis_o[g] * acc;
        sc[i] = s;
        unsigned int u = __float_as_uint(s);
        u ^= (u >> 31) ? 0xFFFFFFFFu : 0x80000000u;
        keys[i] = ((unsigned long long)(~u) << 32) | (unsigned int)i;
    }
    for (int i = n_cur + t; i < 1024; i += 512) keys[i] = 0xFFFFFFFFFFFFFFFFull;
    for (int i = t; i < 1024; i += 512) nidx[i] = -1;
    __syncthreads();
    // 2. bitonic sort (1024 keys, 512 threads)
    for (int size = 2; size <= 1024; size <<= 1) {
        for (int stride = size >> 1; stride > 0; stride >>= 1) {
            int pos = 2 * t - (t & (stride - 1));
            int q = pos + stride;
            bool up = ((pos & size) == 0);
            unsigned long long a = keys[pos], c = keys[q];
            if ((a > c) == up) { keys[pos] = c; keys[q] = a; }
            __syncthreads();
        }
    }
    // 3. local new-index map
    for (int j = t; j < k; j += 512) nidx[(int)(keys[j] & 0xFFFFFFFFull)] = j;
    __syncthreads();
    // 4. gather + gate + readout (rg = row group, f = feature)
    int rg = t >> 6, f = t & 63;
    float mx = -3.402823466e+38f, sm = 0.f;
    for (int j = rg; j < k; j += 8) {
        int ol = (int)(keys[j] & 0xFFFFFFFFull);
        float gv = tanhf(sc[ol]);
        float v = A[(size_t)(nbase + ol) * 64 + f] * gv;
        B[((size_t)b * k + j) * 64 + f] = v;
        mx = fmaxf(mx, v);
        sm += v;
    }
    rred[t] = mx;
    __syncthreads();
    if (t < 64) {
        float m = rred[t];
#pragma unroll
        for (int r = 1; r < 8; r++) m = fmaxf(m, rred[t + 64 * r]);
        rbuf[b * 128 + t] = m;
    }
    __syncthreads();
    rred[t] = sm;
    __syncthreads();
    if (t < 64) {
        float s = rred[t];
#pragma unroll
        for (int r = 1; r < 8; r++) s += rred[t + 64 * r];
        rbuf[b * 128 + 64 + t] = s / (float)k;
    }
    if (!write_next) return;
    // 5. count surviving neighbors per new node
    for (int i = t; i < 1024; i += 512) sA[i] = 0;
    __syncthreads();
    for (int j = t; j < k; j += 512) {
        int ol = (int)(keys[j] & 0xFFFFFFFFull);
        int g = nbase + ol;
        int st = rp_o[g], dc = cnt_o[g];
        int c = 0;
        for (int q = 0; q < dc; q++)
            if (nidx[csr_o[st + q] - nbase] >= 0) c++;
        sA[j] = c;
        cnt_n[b * k + j] = c;
        dis_n[b * k + j] = rsqrtf((float)c + 1.0f);
    }
    __syncthreads();
    // 6. scan counts, write filtered+renamed CSR (per-graph slot base b*EPG)
    int* pin = sA; int* pout = sB;
    for (int off = 1; off < 1024; off <<= 1) {
        for (int i = t; i < 1024; i += 512)
            pout[i] = pin[i] + ((i >= off) ? pin[i - off] : 0);
        __syncthreads();
        int* tmp = pin; pin = pout; pout = tmp;
    }
    for (int j = t; j < k; j += 512) {
        int c = cnt_n[b * k + j];
        int ex = pin[j] - c;
        rp_n[b * k + j] = b * EPG + ex;
        int ol = (int)(keys[j] & 0xFFFFFFFFull);
        int g = nbase + ol;
        int st = rp_o[g], dc = cnt_o[g];
        int p = b * EPG + ex;
        for (int q = 0; q < dc; q++) {
            int nl = nidx[csr_o[st + q] - nbase];
            if (nl >= 0) csr_n[p++] = b * k + nl;
        }
    }
}

// ---------------- final MLP ----------------
__global__ void k_mlp(const float* __restrict__ r1, const float* __restrict__ r2,
                      const float* __restrict__ r3,
                      const float* __restrict__ L1w, const float* __restrict__ L1b,
                      const float* __restrict__ L2w, const float* __restrict__ L2b,
                      const float* __restrict__ L3w, const float* __restrict__ L3b,
                      float* __restrict__ out) {
    __shared__ float zs[128], h1[64], h2[32], os[10];
    __shared__ float lse;
    int b = blockIdx.x, t = threadIdx.x;
    zs[t] = r1[b * 128 + t] + r2[b * 128 + t] + r3[b * 128 + t];
    zs[t + 64] = r1[b * 128 + 64 + t] + r2[b * 128 + 64 + t] + r3[b * 128 + 64 + t];
    __syncthreads();
    {
        float acc = L1b[t];
        for (int j = 0; j < 128; j++) acc += zs[j] * L1w[j * 64 + t];
        h1[t] = fmaxf(acc, 0.f);
    }
    __syncthreads();
    if (t < 32) {
        float a = L2b[t];
        for (int j = 0; j < 64; j++) a += h1[j] * L2w[j * 32 + t];
        h2[t] = fmaxf(a, 0.f);
    }
    __syncthreads();
    if (t < 10) {
        float a = L3b[t];
        for (int j = 0; j < 32; j++) a += h2[j] * L3w[j * 10 + t];
        os[t] = a;
    }
    __syncthreads();
    if (t == 0) {
        float mx = os[0];
        for (int j = 1; j < 10; j++) mx = fmaxf(mx, os[j]);
        float s = 0.f;
        for (int j = 0; j < 10; j++) s += expf(os[j] - mx);
        lse = mx + logf(s);
    }
    __syncthreads();
    if (t < 10) out[b * 10 + t] = os[t] - lse;
}

// ---------------- host orchestration ----------------
extern "C" void kernel_launch(void* const* d_in, const int* in_sizes, int n_in,
                              void* d_out, int out_size) {
    const float* x   = (const float*)d_in[0];
    const int* esrc  = (const int*)d_in[1];
    const int* edst  = (const int*)d_in[2];
    const float* W1  = (const float*)d_in[3];
    const float* b1  = (const float*)d_in[4];
    const float* Wp1 = (const float*)d_in[5];
    const float* bp1 = (const float*)d_in[6];
    const float* W2  = (const float*)d_in[7];
    const float* b2  = (const float*)d_in[8];
    const float* Wp2 = (const float*)d_in[9];
    const float* bp2 = (const float*)d_in[10];
    const float* W3  = (const float*)d_in[11];
    const float* b3  = (const float*)d_in[12];
    const float* Wp3 = (const float*)d_in[13];
    const float* bp3 = (const float*)d_in[14];
    const float* L1w = (const float*)d_in[15];
    const float* L1b = (const float*)d_in[16];
    const float* L2w = (const float*)d_in[17];
    const float* L2b = (const float*)d_in[18];
    const float* L3w = (const float*)d_in[19];
    const float* L3b = (const float*)d_in[20];
    float* out = (float*)d_out;

    float *pA, *pB, *pxw, *pdisA, *pdisB, *psxws, *pr1, *pr2, *pr3;
    int *prpA, *prpB, *pcntA, *pcntB, *pcsrA, *pcsrB;
    cudaGetSymbolAddress((void**)&pA, g_A);
    cudaGetSymbolAddress((void**)&pB, g_B);
    cudaGetSymbolAddress((void**)&pxw, g_xw);
    cudaGetSymbolAddress((void**)&pdisA, g_disA);
    cudaGetSymbolAddress((void**)&pdisB, g_disB);
    cudaGetSymbolAddress((void**)&psxws, g_sxws);
    cudaGetSymbolAddress((void**)&prpA, g_rpA);
    cudaGetSymbolAddress((void**)&prpB, g_rpB);
    cudaGetSymbolAddress((void**)&pcntA, g_cntA);
    cudaGetSymbolAddress((void**)&pcntB, g_cntB);
    cudaGetSymbolAddress((void**)&pcsrA, g_csrA);
    cudaGetSymbolAddress((void**)&pcsrB, g_csrB);
    cudaGetSymbolAddress((void**)&pr1, g_r1);
    cudaGetSymbolAddress((void**)&pr2, g_r2);
    cudaGetSymbolAddress((void**)&pr3, g_r3);

    // Stage-1 CSR from raw edge list (per-graph blocks, smem only)
    k_csr0<<<BGRAPHS, 512>>>(esrc, edst, prpA, pcntA, pdisA, pcsrA);

    // ---- stage 1 ----
    k_gemm64s<<<NT1 / 64, 256>>>(x, W1, pdisA, pxw);
    k_agg<<<NT1 / 8, 256>>>((const float2*)pxw, prpA, pcntA, pdisA, pcsrA,
                            b1, Wp1, (float2*)pA, psxws, NT1);
    k_pool<<<BGRAPHS, 512>>>(pA, psxws, pdisA, prpA, pcntA, pcsrA, bp1,
                             N0, K1, 1, pB, pr1, prpB, pcntB, pdisB, pcsrB);

    // ---- stage 2 ----
    k_gemm64s<<<NT2 / 64, 256>>>(pB, W2, pdisB, pxw);
    k_agg<<<NT2 / 8, 256>>>((const float2*)pxw, prpB, pcntB, pdisB, pcsrB,
                            b2, Wp2, (float2*)pA, psxws, NT2);
    k_pool<<<BGRAPHS, 512>>>(pA, psxws, pdisB, prpB, pcntB, pcsrB, bp2,
                             K1, K2, 1, pB, pr2, prpA, pcntA, pdisA, pcsrA);

    // ---- stage 3 ----
    k_gemm64s<<<NT3 / 64, 256>>>(pB, W3, pdisA, pxw);
    k_agg<<<NT3 / 8, 256>>>((const float2*)pxw, prpA, pcntA, pdisA, pcsrA,
                            b3, Wp3, (float2*)pA, psxws, NT3);
    k_pool<<<BGRAPHS, 512>>>(pA, psxws, pdisA, prpA, pcntA, pcsrA, bp3,
                             K2, K3, 0, pB, pr3, prpB, pcntB, pdisB, pcsrB);

    k_mlp<<<BGRAPHS, 64>>>(pr1, pr2, pr3, L1w, L1b, L2w, L2b, L3w, L3b, out);
}

// round 4
// speedup vs baseline: 2.3306x; 1.1070x over previous
#include <cuda_runtime.h>
#include <math.h>

// ---------------- problem constants ----------------
#define BGRAPHS 128
#define N0      1024
#define EPG     8192                  // edges per graph
#define EMAX    1048576
#define NT1     (BGRAPHS * N0)        // 131072
#define K1      820
#define NT2     (BGRAPHS * K1)        // 104960
#define K2      656
#define NT3     (BGRAPHS * K2)        // 83968
#define K3      525

// ---------------- device scratch ----------------
__device__ float g_A[NT1 * 64];       // conv output h
__device__ float g_xw[NT1 * 64];      // GEMM output, pre-scaled by dis[row]
__device__ float g_disA[NT1], g_disB[NT1];
__device__ float g_sxws[NT1];
__device__ int   g_rpA[NT1], g_rpB[NT1];
__device__ int   g_cntA[NT1], g_cntB[NT1];
__device__ int   g_csrA[EMAX], g_csrB[EMAX];
__device__ int   g_perm[NT1];
__device__ float g_gate[NT1];
__device__ float g_r1[BGRAPHS * 128], g_r2[BGRAPHS * 128], g_r3[BGRAPHS * 128];

// ---- block-wide exclusive scan of 1024 ints, 512 threads, in-place OK ----
__device__ __forceinline__ void block_exscan_1024(int* data, int* warpsums, int t) {
    int a = data[2 * t], bval = data[2 * t + 1];
    int s = a + bval;
    int lane = t & 31, wid = t >> 5;
    int v = s;
#pragma unroll
    for (int off = 1; off < 32; off <<= 1) {
        int u = __shfl_up_sync(0xffffffffu, v, off);
        if (lane >= off) v += u;
    }
    if (lane == 31) warpsums[wid] = v;
    __syncthreads();
    if (t < 32) {
        int w = (t < 16) ? warpsums[t] : 0;
#pragma unroll
        for (int off = 1; off < 16; off <<= 1) {
            int u = __shfl_up_sync(0xffffffffu, w, off);
            if (lane >= off) w += u;
        }
        if (t < 16) warpsums[t] = w;  // inclusive warp totals
    }
    __syncthreads();
    int base = (wid > 0) ? warpsums[wid - 1] : 0;
    int excl = base + v - s;
    data[2 * t] = excl;
    data[2 * t + 1] = excl + a;
    __syncthreads();
}

// ---------------- stage-1 CSR build: one block per graph ----------
__global__ void __launch_bounds__(512) k_csr0(
    const int* __restrict__ src, const int* __restrict__ dst,
    int* __restrict__ rowptr, int* __restrict__ cnt, float* __restrict__ dis,
    int* __restrict__ csr) {
    __shared__ int scnt[1024];
    __shared__ int sofs[1024];
    __shared__ int scur[1024];
    __shared__ int warpsums[17];
    int b = blockIdx.x, t = threadIdx.x;
    int ebase = b * EPG, nbase = b * N0;
    for (int i = t; i < 1024; i += 512) scnt[i] = 0;
    __syncthreads();
    for (int e = t; e < EPG; e += 512)
        atomicAdd(&scnt[dst[ebase + e] - nbase], 1);
    __syncthreads();
    for (int i = t; i < 1024; i += 512) sofs[i] = scnt[i];
    __syncthreads();
    block_exscan_1024(sofs, warpsums, t);
    for (int i = t; i < 1024; i += 512) {
        int c = scnt[i];
        int ex = sofs[i];
        rowptr[nbase + i] = ebase + ex;
        cnt[nbase + i] = c;
        dis[nbase + i] = rsqrtf((float)c + 1.0f);
        scur[i] = ex;
    }
    __syncthreads();
    for (int e = t; e < EPG; e += 512) {
        int d = dst[ebase + e] - nbase;
        int p = atomicAdd(&scur[d], 1);
        csr[ebase + p] = src[ebase + e];
    }
}

// ---------------- GEMM: C[r] = (gather(A)[r] @ W) * scale[r] ----------------
template <bool GATHER>
__global__ void __launch_bounds__(256) k_gemm64g(
    const float* __restrict__ A, const float* __restrict__ W,
    const float* __restrict__ scale, const int* __restrict__ perm,
    const float* __restrict__ gate, float* __restrict__ C) {
    __shared__ float As[64][65];
    __shared__ float Ws[64][64];
    int t = threadIdx.x;
    int r0 = blockIdx.x * 64;
    for (int i = t; i < 4096; i += 256) Ws[i >> 6][i & 63] = W[i];
    for (int i = t; i < 1024; i += 256) {
        int r = i >> 4, c4 = i & 15;
        int g = r0 + r;
        float gt = 1.f;
        int row = g;
        if (GATHER) { row = perm[g]; gt = gate[g]; }
        float4 v = ((const float4*)A)[(size_t)row * 16 + c4];
        As[r][c4 * 4 + 0] = v.x * gt;
        As[r][c4 * 4 + 1] = v.y * gt;
        As[r][c4 * 4 + 2] = v.z * gt;
        As[r][c4 * 4 + 3] = v.w * gt;
    }
    __syncthreads();
    int tx = t & 15, ty = t >> 4;
    float acc[4][4] = {};
#pragma unroll 16
    for (int k = 0; k < 64; k++) {
        float4 w = *(const float4*)&Ws[k][tx * 4];
        float a0 = As[ty * 4 + 0][k];
        float a1 = As[ty * 4 + 1][k];
        float a2 = As[ty * 4 + 2][k];
        float a3 = As[ty * 4 + 3][k];
        acc[0][0] += a0 * w.x; acc[0][1] += a0 * w.y; acc[0][2] += a0 * w.z; acc[0][3] += a0 * w.w;
        acc[1][0] += a1 * w.x; acc[1][1] += a1 * w.y; acc[1][2] += a1 * w.z; acc[1][3] += a1 * w.w;
        acc[2][0] += a2 * w.x; acc[2][1] += a2 * w.y; acc[2][2] += a2 * w.z; acc[2][3] += a2 * w.w;
        acc[3][0] += a3 * w.x; acc[3][1] += a3 * w.y; acc[3][2] += a3 * w.z; acc[3][3] += a3 * w.w;
    }
#pragma unroll
    for (int i = 0; i < 4; i++) {
        int r = r0 + ty * 4 + i;
        float s = scale[r];
        *(float4*)&C[(size_t)r * 64 + tx * 4] =
            make_float4(acc[i][0] * s, acc[i][1] * s, acc[i][2] * s, acc[i][3] * s);
    }
}

// ---------------- fused aggregation: conv + bias + relu + score projection ------
__global__ void k_agg(const float2* __restrict__ xws2, const int* __restrict__ rowptr,
                      const int* __restrict__ cnt, const float* __restrict__ dis,
                      const int* __restrict__ csr,
                      const float* __restrict__ b, const float* __restrict__ Wp,
                      float2* __restrict__ h2, float* __restrict__ sxws, int n) {
    int w = (blockIdx.x * blockDim.x + threadIdx.x) >> 5;
    if (w >= n) return;
    int lane = threadIdx.x & 31;
    int start = rowptr[w], dc = cnt[w];
    float2 acc = xws2[(size_t)w * 32 + lane];  // self message (pre-scaled by dis)
    for (int base = 0; base < dc; base += 32) {
        int rem = dc - base;
        int s = (lane < rem) ? csr[start + base + lane] : 0;
        int lim = rem < 32 ? rem : 32;
        for (int j = 0; j < lim; j++) {
            int sj = __shfl_sync(0xffffffffu, s, j);
            float2 v = xws2[(size_t)sj * 32 + lane];
            acc.x += v.x;
            acc.y += v.y;
        }
    }
    float di = dis[w];
    float2 o;
    o.x = fmaxf(acc.x * di + b[2 * lane], 0.f);
    o.y = fmaxf(acc.y * di + b[2 * lane + 1], 0.f);
    h2[(size_t)w * 32 + lane] = o;
    float sa = o.x * Wp[2 * lane] + o.y * Wp[2 * lane + 1];
#pragma unroll
    for (int off = 16; off > 0; off >>= 1) sa += __shfl_xor_sync(0xffffffffu, sa, off);
    if (lane == 0) sxws[w] = sa * di;
}

// ---------------- fused per-graph pool: score + radix top-k + readout + CSR filter
__global__ void __launch_bounds__(512) k_pool(
    const float* __restrict__ A, const float* __restrict__ sxws,
    const float* __restrict__ dis_o, const int* __restrict__ rp_o,
    const int* __restrict__ cnt_o, const int* __restrict__ csr_o,
    const float* __restrict__ bp, int n_cur, int k, int write_next,
    float* __restrict__ rbuf, int* __restrict__ perm_g, float* __restrict__ gate_g,
    int* __restrict__ rp_n, int* __restrict__ cnt_n, float* __restrict__ dis_n,
    int* __restrict__ csr_n) {
    __shared__ float sc[1024];
    __shared__ unsigned su[1024];     // orderable keys; later: gate per new id
    __shared__ int sflag[1024];       // packed flags / counts (scanned in place)
    __shared__ int nidx[1024];
    __shared__ int oldof[1024];
    __shared__ int hist[256];
    __shared__ int warpsums[17];
    __shared__ int sh_c, sh_base;
    __shared__ float rred[512];
    int b = blockIdx.x, t = threadIdx.x;
    int nbase = b * n_cur;
    float bp0 = bp[0];
    // 1. scores
    for (int i = t; i < n_cur; i += 512) {
        int g = nbase + i;
        int st = rp_o[g], dc = cnt_o[g];
        float acc = sxws[g];
        for (int q = 0; q < dc; q++) acc += sxws[csr_o[st + q]];
        float s = bp0 + dis_o[g] * acc;
        sc[i] = s;
        unsigned u = __float_as_uint(s);
        u ^= (u >> 31) ? 0xFFFFFFFFu : 0x80000000u;  // ascending-orderable
        su[i] = u;
    }
    __syncthreads();
    // 2. radix select the key of ascending rank R = n_cur - k  (the k-th largest)
    int R = n_cur - k;
    unsigned prefix = 0, maskhi = 0;
#pragma unroll
    for (int pass = 3; pass >= 0; pass--) {
        int shift = pass * 8;
        if (t < 256) hist[t] = 0;
        __syncthreads();
        for (int i = t; i < n_cur; i += 512) {
            unsigned u = su[i];
            if ((u & maskhi) == prefix) atomicAdd(&hist[(u >> shift) & 255], 1);
        }
        __syncthreads();
        if (t < 32) {
            int loc[8];
            int s = 0;
#pragma unroll
            for (int j = 0; j < 8; j++) { loc[j] = hist[t * 8 + j]; s += loc[j]; }
            int v = s;
#pragma unroll
            for (int off = 1; off < 32; off <<= 1) {
                int u2 = __shfl_up_sync(0xffffffffu, v, off);
                if ((t & 31) >= off) v += u2;
            }
            int run = v - s;  // exclusive
#pragma unroll
            for (int j = 0; j < 8; j++) {
                if (R >= run && R < run + loc[j]) { sh_c = t * 8 + j; sh_base = run; }
                run += loc[j];
            }
        }
        __syncthreads();
        prefix |= ((unsigned)sh_c) << shift;
        maskhi |= 0xFFu << shift;
        R -= sh_base;
    }
    unsigned thr = prefix;
    // 3. selection flags: packed (gt<<16 | eq), stable compaction by index
    for (int i = t; i < n_cur; i += 512) {
        unsigned u = su[i];
        int gt = (u > thr) ? 1 : 0;
        int eq = (u == thr) ? 1 : 0;
        sflag[i] = (gt << 16) | eq;
    }
    for (int i = n_cur + t; i < 1024; i += 512) sflag[i] = 0;
    __syncthreads();
    block_exscan_1024(sflag, warpsums, t);
    int tot = warpsums[15];
    int quota = k - (tot >> 16);
    for (int i = t; i < n_cur; i += 512) {
        unsigned u = su[i];
        int ex = sflag[i];
        int gtex = ex >> 16, eqex = ex & 0xFFFF;
        int sel = -1;
        if (u > thr) sel = gtex + (eqex < quota ? eqex : quota);
        else if (u == thr && eqex < quota) sel = gtex + eqex;
        nidx[i] = sel;
        if (sel >= 0) oldof[sel] = i;
    }
    __syncthreads();
    // 4. gates + perm (su reused as gate[j]; sc read by old id, su written by new id)
    for (int i = t; i < n_cur; i += 512) {
        int sel = nidx[i];
        if (sel >= 0) {
            float gv = tanhf(sc[i]);
            su[sel] = __float_as_uint(gv);
            perm_g[b * k + sel] = nbase + i;
            gate_g[b * k + sel] = gv;
        }
    }
    __syncthreads();
    // 5. readout: max/mean of gated features over the k kept rows
    int rg = t >> 6, f = t & 63;
    float mx = -3.402823466e+38f, sm = 0.f;
    for (int j = rg; j < k; j += 8) {
        int ol = oldof[j];
        float v = A[(size_t)(nbase + ol) * 64 + f] * __uint_as_float(su[j]);
        mx = fmaxf(mx, v);
        sm += v;
    }
    rred[t] = mx;
    __syncthreads();
    if (t < 64) {
        float m = rred[t];
#pragma unroll
        for (int r = 1; r < 8; r++) m = fmaxf(m, rred[t + 64 * r]);
        rbuf[b * 128 + t] = m;
    }
    __syncthreads();
    rred[t] = sm;
    __syncthreads();
    if (t < 64) {
        float s = rred[t];
#pragma unroll
        for (int r = 1; r < 8; r++) s += rred[t + 64 * r];
        rbuf[b * 128 + 64 + t] = s / (float)k;
    }
    if (!write_next) return;
    // 6. surviving-neighbor counts per new node
    __syncthreads();
    for (int j = t; j < k; j += 512) {
        int ol = oldof[j];
        int g = nbase + ol;
        int st = rp_o[g], dc = cnt_o[g];
        int c = 0;
        for (int q = 0; q < dc; q++)
            if (nidx[csr_o[st + q] - nbase] >= 0) c++;
        sflag[j] = c;
        cnt_n[b * k + j] = c;
        dis_n[b * k + j] = rsqrtf((float)c + 1.0f);
    }
    for (int j = k + t; j < 1024; j += 512) sflag[j] = 0;
    __syncthreads();
    block_exscan_1024(sflag, warpsums, t);
    // 7. write filtered + renamed CSR
    for (int j = t; j < k; j += 512) {
        int ex = sflag[j];
        rp_n[b * k + j] = b * EPG + ex;
        int ol = oldof[j];
        int g = nbase + ol;
        int st = rp_o[g], dc = cnt_o[g];
        int p = b * EPG + ex;
        for (int q = 0; q < dc; q++) {
            int nl = nidx[csr_o[st + q] - nbase];
            if (nl >= 0) csr_n[p++] = b * k + nl;
        }
    }
}

// ---------------- final MLP ----------------
__global__ void k_mlp(const float* __restrict__ r1, const float* __restrict__ r2,
                      const float* __restrict__ r3,
                      const float* __restrict__ L1w, const float* __restrict__ L1b,
                      const float* __restrict__ L2w, const float* __restrict__ L2b,
                      const float* __restrict__ L3w, const float* __restrict__ L3b,
                      float* __restrict__ out) {
    __shared__ float zs[128], h1[64], h2[32], os[10];
    __shared__ float lse;
    int b = blockIdx.x, t = threadIdx.x;
    zs[t] = r1[b * 128 + t] + r2[b * 128 + t] + r3[b * 128 + t];
    zs[t + 64] = r1[b * 128 + 64 + t] + r2[b * 128 + 64 + t] + r3[b * 128 + 64 + t];
    __syncthreads();
    {
        float acc = L1b[t];
        for (int j = 0; j < 128; j++) acc += zs[j] * L1w[j * 64 + t];
        h1[t] = fmaxf(acc, 0.f);
    }
    __syncthreads();
    if (t < 32) {
        float a = L2b[t];
        for (int j = 0; j < 64; j++) a += h1[j] * L2w[j * 32 + t];
        h2[t] = fmaxf(a, 0.f);
    }
    __syncthreads();
    if (t < 10) {
        float a = L3b[t];
        for (int j = 0; j < 32; j++) a += h2[j] * L3w[j * 10 + t];
        os[t] = a;
    }
    __syncthreads();
    if (t == 0) {
        float mx = os[0];
        for (int j = 1; j < 10; j++) mx = fmaxf(mx, os[j]);
        float s = 0.f;
        for (int j = 0; j < 10; j++) s += expf(os[j] - mx);
        lse = mx + logf(s);
    }
    __syncthreads();
    if (t < 10) out[b * 10 + t] = os[t] - lse;
}

// ---------------- host orchestration ----------------
extern "C" void kernel_launch(void* const* d_in, const int* in_sizes, int n_in,
                              void* d_out, int out_size) {
    const float* x   = (const float*)d_in[0];
    const int* esrc  = (const int*)d_in[1];
    const int* edst  = (const int*)d_in[2];
    const float* W1  = (const float*)d_in[3];
    const float* b1  = (const float*)d_in[4];
    const float* Wp1 = (const float*)d_in[5];
    const float* bp1 = (const float*)d_in[6];
    const float* W2  = (const float*)d_in[7];
    const float* b2  = (const float*)d_in[8];
    const float* Wp2 = (const float*)d_in[9];
    const float* bp2 = (const float*)d_in[10];
    const float* W3  = (const float*)d_in[11];
    const float* b3  = (const float*)d_in[12];
    const float* Wp3 = (const float*)d_in[13];
    const float* bp3 = (const float*)d_in[14];
    const float* L1w = (const float*)d_in[15];
    const float* L1b = (const float*)d_in[16];
    const float* L2w = (const float*)d_in[17];
    const float* L2b = (const float*)d_in[18];
    const float* L3w = (const float*)d_in[19];
    const float* L3b = (const float*)d_in[20];
    float* out = (float*)d_out;

    float *pA, *pxw, *pdisA, *pdisB, *psxws, *pgate, *pr1, *pr2, *pr3;
    int *prpA, *prpB, *pcntA, *pcntB, *pcsrA, *pcsrB, *pperm;
    cudaGetSymbolAddress((void**)&pA, g_A);
    cudaGetSymbolAddress((void**)&pxw, g_xw);
    cudaGetSymbolAddress((void**)&pdisA, g_disA);
    cudaGetSymbolAddress((void**)&pdisB, g_disB);
    cudaGetSymbolAddress((void**)&psxws, g_sxws);
    cudaGetSymbolAddress((void**)&pgate, g_gate);
    cudaGetSymbolAddress((void**)&pperm, g_perm);
    cudaGetSymbolAddress((void**)&prpA, g_rpA);
    cudaGetSymbolAddress((void**)&prpB, g_rpB);
    cudaGetSymbolAddress((void**)&pcntA, g_cntA);
    cudaGetSymbolAddress((void**)&pcntB, g_cntB);
    cudaGetSymbolAddress((void**)&pcsrA, g_csrA);
    cudaGetSymbolAddress((void**)&pcsrB, g_csrB);
    cudaGetSymbolAddress((void**)&pr1, g_r1);
    cudaGetSymbolAddress((void**)&pr2, g_r2);
    cudaGetSymbolAddress((void**)&pr3, g_r3);

    k_csr0<<<BGRAPHS, 512>>>(esrc, edst, prpA, pcntA, pdisA, pcsrA);

    // ---- stage 1 ----
    k_gemm64g<false><<<NT1 / 64, 256>>>(x, W1, pdisA, nullptr, nullptr, pxw);
    k_agg<<<NT1 / 8, 256>>>((const float2*)pxw, prpA, pcntA, pdisA, pcsrA,
                            b1, Wp1, (float2*)pA, psxws, NT1);
    k_pool<<<BGRAPHS, 512>>>(pA, psxws, pdisA, prpA, pcntA, pcsrA, bp1,
                             N0, K1, 1, pr1, pperm, pgate,
                             prpB, pcntB, pdisB, pcsrB);

    // ---- stage 2 (gemm gathers pooled rows from h of stage 1) ----
    k_gemm64g<true><<<NT2 / 64, 256>>>(pA, W2, pdisB, pperm, pgate, pxw);
    k_agg<<<NT2 / 8, 256>>>((const float2*)pxw, prpB, pcntB, pdisB, pcsrB,
                            b2, Wp2, (float2*)pA, psxws, NT2);
    k_pool<<<BGRAPHS, 512>>>(pA, psxws, pdisB, prpB, pcntB, pcsrB, bp2,
                             K1, K2, 1, pr2, pperm, pgate,
                             prpA, pcntA, pdisA, pcsrA);

    // ---- stage 3 ----
    k_gemm64g<true><<<NT3 / 64, 256>>>(pA, W3, pdisA, pperm, pgate, pxw);
    k_agg<<<NT3 / 8, 256>>>((const float2*)pxw, prpA, pcntA, pdisA, pcsrA,
                            b3, Wp3, (float2*)pA, psxws, NT3);
    k_pool<<<BGRAPHS, 512>>>(pA, psxws, pdisA, prpA, pcntA, pcsrA, bp3,
                             K2, K3, 0, pr3, pperm, pgate,
                             prpB, pcntB, pdisB, pcsrB);

    k_mlp<<<BGRAPHS, 64>>>(pr1, pr2, pr3, L1w, L1b, L2w, L2b, L3w, L3b, out);
}